// round 3
// baseline (speedup 1.0000x reference)
#include <cuda_runtime.h>
#include <math.h>

#define PN   512
#define HIMG 256
#define WIMG 256
#define FXC  256.0f
#define FYC  256.0f
#define SH_C0 0.28209479177387814f

// Sorted per-gaussian params (front-to-back order)
__device__ float g_mx[PN], g_my[PN], g_A[PN], g_B[PN], g_C[PN];
__device__ float g_op[PN], g_cr[PN], g_cg[PN], g_cb[PN], g_rc[PN];

__global__ __launch_bounds__(PN)
void preprocess_kernel(const float* __restrict__ pts,
                       const float* __restrict__ scales,
                       const float* __restrict__ rots,
                       const float* __restrict__ opac_in,
                       const float* __restrict__ shs,
                       const float* __restrict__ vm,
                       float* out_vsp, float* out_radii)
{
    __shared__ float skey[PN];
    __shared__ int   sidx[PN];
    __shared__ float smx[PN], smy[PN], sA[PN], sB[PN], sC[PN];
    __shared__ float sop[PN], scr[PN], scg[PN], scb[PN], src2[PN];

    const int i = threadIdx.x;

    // ---- per-gaussian math ----
    float px = pts[3*i+0], py = pts[3*i+1], pz = pts[3*i+2];
    float sx = expf(scales[3*i+0]), sy = expf(scales[3*i+1]), sz = expf(scales[3*i+2]);
    float op = 1.0f / (1.0f + expf(-opac_in[i]));

    float qr = rots[4*i+0], qx = rots[4*i+1], qy = rots[4*i+2], qz = rots[4*i+3];
    float qn = rsqrtf(qr*qr + qx*qx + qy*qy + qz*qz);
    qr *= qn; qx *= qn; qy *= qn; qz *= qn;

    float R00 = 1.f - 2.f*(qy*qy + qz*qz), R01 = 2.f*(qx*qy - qr*qz), R02 = 2.f*(qx*qz + qr*qy);
    float R10 = 2.f*(qx*qy + qr*qz), R11 = 1.f - 2.f*(qx*qx + qz*qz), R12 = 2.f*(qy*qz - qr*qx);
    float R20 = 2.f*(qx*qz - qr*qy), R21 = 2.f*(qy*qz + qr*qx), R22 = 1.f - 2.f*(qx*qx + qy*qy);

    // M = R * diag(s)
    float M00 = R00*sx, M01 = R01*sy, M02 = R02*sz;
    float M10 = R10*sx, M11 = R11*sy, M12 = R12*sz;
    float M20 = R20*sx, M21 = R21*sy, M22 = R22*sz;

    // Sigma = M M^T (symmetric)
    float S00 = M00*M00 + M01*M01 + M02*M02;
    float S01 = M00*M10 + M01*M11 + M02*M12;
    float S02 = M00*M20 + M01*M21 + M02*M22;
    float S11 = M10*M10 + M11*M11 + M12*M12;
    float S12 = M10*M20 + M11*M21 + M12*M22;
    float S22 = M20*M20 + M21*M21 + M22*M22;

    // view transform (viewmat row-major 4x4)
    float W00 = vm[0], W01 = vm[1], W02 = vm[2],  W03 = vm[3];
    float W10 = vm[4], W11 = vm[5], W12 = vm[6],  W13 = vm[7];
    float W20 = vm[8], W21 = vm[9], W22 = vm[10], W23 = vm[11];

    float t0 = W00*px + W01*py + W02*pz + W03;
    float t1 = W10*px + W11*py + W12*pz + W13;
    float t2 = W20*px + W21*py + W22*pz + W23;

    bool vis = (t2 > 0.2f);
    float tz = vis ? t2 : 1.0f;

    const float lim = 1.3f * 0.5f;
    float txtz = fminf(fmaxf(t0 / tz, -lim), lim) * tz;
    float tytz = fminf(fmaxf(t1 / tz, -lim), lim) * tz;

    float J00 = FXC / tz;
    float J02 = -FXC * txtz / (tz * tz);
    float J11 = FYC / tz;
    float J12 = -FYC * tytz / (tz * tz);

    // Tm = J @ W (2x3)
    float T00 = J00*W00 + J02*W20;
    float T01 = J00*W01 + J02*W21;
    float T02 = J00*W02 + J02*W22;
    float T10 = J11*W10 + J12*W20;
    float T11 = J11*W11 + J12*W21;
    float T12 = J11*W12 + J12*W22;

    // cov = Tm Sigma Tm^T
    float V00 = S00*T00 + S01*T01 + S02*T02;  // Sigma * T0^T
    float V01 = S01*T00 + S11*T01 + S12*T02;
    float V02 = S02*T00 + S12*T01 + S22*T02;
    float U00 = S00*T10 + S01*T11 + S02*T12;  // Sigma * T1^T
    float U01 = S01*T10 + S11*T11 + S12*T12;
    float U02 = S02*T10 + S12*T11 + S22*T12;

    float cov00 = T00*V00 + T01*V01 + T02*V02;
    float cov01 = T10*V00 + T11*V01 + T12*V02;
    float cov11 = T10*U00 + T11*U01 + T12*U02;

    float det_orig = cov00*cov11 - cov01*cov01;
    float a = cov00 + 0.3f;
    float c = cov11 + 0.3f;
    float b = cov01;
    float det = a*c - b*b;
    vis = vis && (det > 0.0f);
    float dets = (det > 0.0f) ? det : 1.0f;
    float comp = sqrtf(fmaxf(det_orig / dets, 0.0f));
    float opEff = op * comp * (vis ? 1.0f : 0.0f);

    float conA = c / dets, conB = -b / dets, conC = a / dets;
    float mid = 0.5f * (a + c);
    float lam = mid + sqrtf(fmaxf(mid*mid - det, 0.1f));
    float radii = vis ? ceilf(3.0f * sqrtf(lam)) : 0.0f;

    float mx = FXC * t0 / tz + (WIMG - 1) * 0.5f;
    float my = FYC * t1 / tz + (HIMG - 1) * 0.5f;

    float cr = fmaxf(shs[3*i+0] * SH_C0 + 0.5f, 0.0f);
    float cg = fmaxf(shs[3*i+1] * SH_C0 + 0.5f, 0.0f);
    float cb = fmaxf(shs[3*i+2] * SH_C0 + 0.5f, 0.0f);

    // Conservative cutoff: alpha>=1/255 requires d^2 <= 2*ln(255*op)*lam
    float rc;
    if (255.0f * opEff >= 1.0f)
        rc = fmaxf(2.0f * logf(255.0f * opEff), 0.0f) * lam * 1.01f + 1e-3f;
    else
        rc = -1.0f;

    // aux outputs (original order)
    if (out_radii) out_radii[i] = radii;
    if (out_vsp) { out_vsp[3*i+0] = 0.f; out_vsp[3*i+1] = 0.f; out_vsp[3*i+2] = 0.f; }

    // stash for sort
    smx[i] = mx; smy[i] = my; sA[i] = conA; sB[i] = conB; sC[i] = conC;
    sop[i] = opEff; scr[i] = cr; scg[i] = cg; scb[i] = cb; src2[i] = rc;
    skey[i] = vis ? t2 : INFINITY;
    sidx[i] = i;
    __syncthreads();

    // ---- bitonic sort on (key, idx) == stable argsort of key ----
    for (int k = 2; k <= PN; k <<= 1) {
        for (int j = k >> 1; j > 0; j >>= 1) {
            int ixj = i ^ j;
            if (ixj > i) {
                bool up = ((i & k) == 0);
                float ka = skey[i], kb = skey[ixj];
                int ia = sidx[i], ib = sidx[ixj];
                bool gt = (ka > kb) || (ka == kb && ia > ib);
                if (up ? gt : !gt) {
                    skey[i] = kb; skey[ixj] = ka;
                    sidx[i] = ib; sidx[ixj] = ia;
                }
            }
            __syncthreads();
        }
    }

    int s = sidx[i];
    g_mx[i] = smx[s]; g_my[i] = smy[s];
    g_A[i] = sA[s]; g_B[i] = sB[s]; g_C[i] = sC[s];
    g_op[i] = sop[s]; g_cr[i] = scr[s]; g_cg[i] = scg[s]; g_cb[i] = scb[s];
    g_rc[i] = src2[s];
}

#define CHUNK 256

__global__ __launch_bounds__(256)
void render_kernel(float* __restrict__ out_rgb)
{
    __shared__ float cmx[CHUNK], cmy[CHUNK], cA[CHUNK], cB[CHUNK], cC[CHUNK];
    __shared__ float cop[CHUNK], ccr[CHUNK], ccg[CHUNK], ccb[CHUNK];
    __shared__ int   clist[CHUNK];
    __shared__ int   wcnt[8];

    const int tx = threadIdx.x, ty = threadIdx.y;
    const int t = ty * 16 + tx;
    const int xi = blockIdx.x * 16 + tx;
    const int yi = blockIdx.y * 16 + ty;
    const float x = (float)xi, y = (float)yi;

    const float tx0 = (float)(blockIdx.x * 16);
    const float tx1 = tx0 + 15.0f;
    const float ty0 = (float)(blockIdx.y * 16);
    const float ty1 = ty0 + 15.0f;

    float T = 1.0f, acr = 0.0f, acg = 0.0f, acb = 0.0f;

    for (int base = 0; base < PN; base += CHUNK) {
        __syncthreads();  // protect smem from prior chunk's readers
        int g = base + t;
        float mx = g_mx[g], my = g_my[g], rc = g_rc[g];
        cmx[t] = mx; cmy[t] = my;
        cA[t] = g_A[g]; cB[t] = g_B[g]; cC[t] = g_C[g];
        cop[t] = g_op[g]; ccr[t] = g_cr[g]; ccg[t] = g_cg[g]; ccb[t] = g_cb[g];

        // tile-vs-gaussian conservative test
        float ddx = fmaxf(fmaxf(tx0 - mx, mx - tx1), 0.0f);
        float ddy = fmaxf(fmaxf(ty0 - my, my - ty1), 0.0f);
        bool flag = (rc > 0.0f) && (ddx*ddx + ddy*ddy <= rc);

        unsigned m = __ballot_sync(0xffffffffu, flag);
        int lane = t & 31, w = t >> 5;
        if (lane == 0) wcnt[w] = __popc(m);
        __syncthreads();

        int off = 0;
        #pragma unroll
        for (int k = 0; k < 8; k++) off += (k < w) ? wcnt[k] : 0;
        int total = 0;
        #pragma unroll
        for (int k = 0; k < 8; k++) total += wcnt[k];
        if (flag) {
            int pos = off + __popc(m & ((1u << lane) - 1u));
            clist[pos] = t;
        }
        __syncthreads();

        if (T >= 1e-4f) {
            for (int jj = 0; jj < total; jj++) {
                int li = clist[jj];
                float dx = x - cmx[li];
                float dy = y - cmy[li];
                float power = -0.5f * (cA[li]*dx*dx + cC[li]*dy*dy) - cB[li]*dx*dy;
                if (power > 0.0f) continue;
                float alpha = fminf(0.99f, cop[li] * __expf(power));
                if (alpha < (1.0f / 255.0f)) continue;
                float wgt = alpha * T;
                acr += wgt * ccr[li];
                acg += wgt * ccg[li];
                acb += wgt * ccb[li];
                T *= (1.0f - alpha);
                if (T < 1e-4f) break;
            }
        }
    }

    const int pix = yi * WIMG + xi;
    out_rgb[pix] = acr;
    out_rgb[HIMG * WIMG + pix] = acg;
    out_rgb[2 * HIMG * WIMG + pix] = acb;
}

extern "C" void kernel_launch(void* const* d_in, const int* in_sizes, int n_in,
                              void* d_out, int out_size)
{
    const float* pts    = (const float*)d_in[0];
    const float* scales = (const float*)d_in[1];
    const float* rots   = (const float*)d_in[2];
    const float* opac   = (const float*)d_in[3];
    const float* shs    = (const float*)d_in[4];
    const float* vm     = (const float*)d_in[5];

    float* out = (float*)d_out;
    float* vsp = nullptr;
    float* rad = nullptr;
    const int rgb_n = 3 * HIMG * WIMG;
    if (out_size >= rgb_n + 3 * PN + PN) {
        vsp = out + rgb_n;
        rad = vsp + 3 * PN;
    }

    preprocess_kernel<<<1, PN>>>(pts, scales, rots, opac, shs, vm, vsp, rad);
    dim3 grid(WIMG / 16, HIMG / 16);
    dim3 block(16, 16);
    render_kernel<<<grid, block>>>(out);
}

// round 6
// speedup vs baseline: 1.4514x; 1.4514x over previous
#include <cuda_runtime.h>
#include <math.h>

#define PN   512
#define HIMG 256
#define WIMG 256
#define FXC  256.0f
#define FYC  256.0f
#define SH_C0 0.28209479177387814f

// Unsorted per-gaussian params (original order) + sort keys
__device__ float4 u_q0[PN];                 // mx, my, A, B
__device__ float4 u_q1[PN];                 // C, op, cr, cg
__device__ float2 u_q2[PN];                 // cb, rc
__device__ unsigned long long u_key[PN];

// Sorted (front-to-back)
__device__ float4 s_q0[PN];
__device__ float4 s_q1[PN];
__device__ float2 s_q2[PN];

// Center-first tile ordering (rows/cols by distance from image center)
__constant__ int c_ord[16] = {7,8,6,9,5,10,4,11,3,12,2,13,1,14,0,15};

// ---------------------------------------------------------------------------
// Kernel 1: per-gaussian math (4 blocks x 128 threads)
// ---------------------------------------------------------------------------
__global__ __launch_bounds__(128)
void preprocess_kernel(const float* __restrict__ pts,
                       const float* __restrict__ scales,
                       const float* __restrict__ rots,
                       const float* __restrict__ opac_in,
                       const float* __restrict__ shs,
                       const float* __restrict__ vm,
                       float* out_vsp, float* out_radii)
{
    const int i = blockIdx.x * 128 + threadIdx.x;

    float px = pts[3*i+0], py = pts[3*i+1], pz = pts[3*i+2];
    float sx = expf(scales[3*i+0]), sy = expf(scales[3*i+1]), sz = expf(scales[3*i+2]);
    float op = 1.0f / (1.0f + expf(-opac_in[i]));

    float qr = rots[4*i+0], qx = rots[4*i+1], qy = rots[4*i+2], qz = rots[4*i+3];
    float qn = rsqrtf(qr*qr + qx*qx + qy*qy + qz*qz);
    qr *= qn; qx *= qn; qy *= qn; qz *= qn;

    float R00 = 1.f - 2.f*(qy*qy + qz*qz), R01 = 2.f*(qx*qy - qr*qz), R02 = 2.f*(qx*qz + qr*qy);
    float R10 = 2.f*(qx*qy + qr*qz), R11 = 1.f - 2.f*(qx*qx + qz*qz), R12 = 2.f*(qy*qz - qr*qx);
    float R20 = 2.f*(qx*qz - qr*qy), R21 = 2.f*(qy*qz + qr*qx), R22 = 1.f - 2.f*(qx*qx + qy*qy);

    float M00 = R00*sx, M01 = R01*sy, M02 = R02*sz;
    float M10 = R10*sx, M11 = R11*sy, M12 = R12*sz;
    float M20 = R20*sx, M21 = R21*sy, M22 = R22*sz;

    float S00 = M00*M00 + M01*M01 + M02*M02;
    float S01 = M00*M10 + M01*M11 + M02*M12;
    float S02 = M00*M20 + M01*M21 + M02*M22;
    float S11 = M10*M10 + M11*M11 + M12*M12;
    float S12 = M10*M20 + M11*M21 + M12*M22;
    float S22 = M20*M20 + M21*M21 + M22*M22;

    float W00 = vm[0], W01 = vm[1], W02 = vm[2],  W03 = vm[3];
    float W10 = vm[4], W11 = vm[5], W12 = vm[6],  W13 = vm[7];
    float W20 = vm[8], W21 = vm[9], W22 = vm[10], W23 = vm[11];

    float t0 = W00*px + W01*py + W02*pz + W03;
    float t1 = W10*px + W11*py + W12*pz + W13;
    float t2 = W20*px + W21*py + W22*pz + W23;

    bool vis = (t2 > 0.2f);
    float tz = vis ? t2 : 1.0f;

    const float lim = 1.3f * 0.5f;
    float txtz = fminf(fmaxf(t0 / tz, -lim), lim) * tz;
    float tytz = fminf(fmaxf(t1 / tz, -lim), lim) * tz;

    float J00 = FXC / tz;
    float J02 = -FXC * txtz / (tz * tz);
    float J11 = FYC / tz;
    float J12 = -FYC * tytz / (tz * tz);

    float T00 = J00*W00 + J02*W20;
    float T01 = J00*W01 + J02*W21;
    float T02 = J00*W02 + J02*W22;
    float T10 = J11*W10 + J12*W20;
    float T11 = J11*W11 + J12*W21;
    float T12 = J11*W12 + J12*W22;

    float V00 = S00*T00 + S01*T01 + S02*T02;
    float V01 = S01*T00 + S11*T01 + S12*T02;
    float V02 = S02*T00 + S12*T01 + S22*T02;
    float U00 = S00*T10 + S01*T11 + S02*T12;
    float U01 = S01*T10 + S11*T11 + S12*T12;
    float U02 = S02*T10 + S12*T11 + S22*T12;

    float cov00 = T00*V00 + T01*V01 + T02*V02;
    float cov01 = T10*V00 + T11*V01 + T12*V02;
    float cov11 = T10*U00 + T11*U01 + T12*U02;

    float det_orig = cov00*cov11 - cov01*cov01;
    float a = cov00 + 0.3f;
    float c = cov11 + 0.3f;
    float b = cov01;
    float det = a*c - b*b;
    vis = vis && (det > 0.0f);
    float dets = (det > 0.0f) ? det : 1.0f;
    float comp = sqrtf(fmaxf(det_orig / dets, 0.0f));
    float opEff = op * comp * (vis ? 1.0f : 0.0f);

    float conA = c / dets, conB = -b / dets, conC = a / dets;
    float mid = 0.5f * (a + c);
    float lam = mid + sqrtf(fmaxf(mid*mid - det, 0.1f));
    float radii = vis ? ceilf(3.0f * sqrtf(lam)) : 0.0f;

    float mx = FXC * t0 / tz + (WIMG - 1) * 0.5f;
    float my = FYC * t1 / tz + (HIMG - 1) * 0.5f;

    float cr = fmaxf(shs[3*i+0] * SH_C0 + 0.5f, 0.0f);
    float cg = fmaxf(shs[3*i+1] * SH_C0 + 0.5f, 0.0f);
    float cb = fmaxf(shs[3*i+2] * SH_C0 + 0.5f, 0.0f);

    // Conservative cutoff radius^2: alpha>=1/255 requires d^2 <= 2*ln(255*op)*lam
    float rc;
    if (255.0f * opEff >= 1.0f)
        rc = fmaxf(2.0f * logf(255.0f * opEff), 0.0f) * lam * 1.01f + 1e-3f;
    else
        rc = -1.0f;

    if (out_radii) out_radii[i] = radii;
    if (out_vsp) { out_vsp[3*i+0] = 0.f; out_vsp[3*i+1] = 0.f; out_vsp[3*i+2] = 0.f; }

    u_q0[i] = make_float4(mx, my, conA, conB);
    u_q1[i] = make_float4(conC, opEff, cr, cg);
    u_q2[i] = make_float2(cb, rc);

    // composite key: positive float bit pattern preserves order; index breaks ties
    float keyf = vis ? t2 : INFINITY;
    u_key[i] = ((unsigned long long)__float_as_uint(keyf) << 32) | (unsigned)i;
}

// ---------------------------------------------------------------------------
// Kernel 2: rank sort + scatter (4 blocks x 128 threads)
// ---------------------------------------------------------------------------
__global__ __launch_bounds__(128)
void sort_kernel()
{
    __shared__ unsigned long long sk[PN];
    const int t = threadIdx.x;
    const int i = blockIdx.x * 128 + t;

    #pragma unroll
    for (int j = t; j < PN; j += 128) sk[j] = u_key[j];
    __syncthreads();

    const unsigned long long ki = sk[i];
    int cnt = 0;
    #pragma unroll 8
    for (int j = 0; j < PN; j++) cnt += (sk[j] < ki) ? 1 : 0;

    s_q0[cnt] = u_q0[i];
    s_q1[cnt] = u_q1[i];
    s_q2[cnt] = u_q2[i];
}

// ---------------------------------------------------------------------------
// Kernel 3: tiled render (256 blocks x 256 threads, 16x16 tiles)
// ---------------------------------------------------------------------------
__global__ __launch_bounds__(256)
void render_kernel(float* __restrict__ out_rgb)
{
    __shared__ float4 c0[PN];     // mx, my, A, B
    __shared__ float4 c1[PN];     // C, op, cr, cg
    __shared__ float  ccb[PN];    // cb
    __shared__ int    wcnt[16];

    const int t = threadIdx.x;
    const int bid = blockIdx.x;
    const int tilex = c_ord[bid & 15];
    const int tiley = c_ord[bid >> 4];

    const float tx0 = (float)(tilex * 16);
    const float tx1 = tx0 + 15.0f;
    const float ty0 = (float)(tiley * 16);
    const float ty1 = ty0 + 15.0f;

    // ---- cull both halves of sorted list ----
    float4 q0a = s_q0[t];
    float2 q2a = s_q2[t];
    float4 q0b = s_q0[t + 256];
    float2 q2b = s_q2[t + 256];

    float dxa = fmaxf(fmaxf(tx0 - q0a.x, q0a.x - tx1), 0.0f);
    float dya = fmaxf(fmaxf(ty0 - q0a.y, q0a.y - ty1), 0.0f);
    bool flagA = (q2a.y > 0.0f) && (dxa*dxa + dya*dya <= q2a.y);

    float dxb = fmaxf(fmaxf(tx0 - q0b.x, q0b.x - tx1), 0.0f);
    float dyb = fmaxf(fmaxf(ty0 - q0b.y, q0b.y - ty1), 0.0f);
    bool flagB = (q2b.y > 0.0f) && (dxb*dxb + dyb*dyb <= q2b.y);

    const unsigned mA = __ballot_sync(0xffffffffu, flagA);
    const unsigned mB = __ballot_sync(0xffffffffu, flagB);
    const int lane = t & 31, w = t >> 5;
    if (lane == 0) { wcnt[w] = __popc(mA); wcnt[8 + w] = __popc(mB); }
    __syncthreads();

    int offA = 0, tot1 = 0, offB = 0, total = 0;
    #pragma unroll
    for (int k = 0; k < 8; k++) {
        int ca = wcnt[k], cbn = wcnt[8 + k];
        offA += (k < w) ? ca : 0;
        offB += (k < w) ? cbn : 0;
        tot1 += ca;
        total += ca + cbn;
    }
    offB += tot1;

    if (flagA) {
        int p = offA + __popc(mA & ((1u << lane) - 1u));
        c0[p] = q0a;
        c1[p] = s_q1[t];
        ccb[p] = q2a.x;
    }
    if (flagB) {
        int p = offB + __popc(mB & ((1u << lane) - 1u));
        c0[p] = q0b;
        c1[p] = s_q1[t + 256];
        ccb[p] = q2b.x;
    }
    __syncthreads();

    // ---- blend (branchless, T-chain only loop dependency) ----
    const int xi = tilex * 16 + (t & 15);
    const int yi = tiley * 16 + (t >> 4);
    const float x = (float)xi, y = (float)yi;

    float T = 1.0f, ar = 0.0f, ag = 0.0f, ab = 0.0f;

    for (int jj = 0; jj < total; jj++) {
        float4 a0 = c0[jj];
        float4 a1 = c1[jj];
        float cbv = ccb[jj];
        float dx = x - a0.x;
        float dy = y - a0.y;
        float power = -0.5f * (a0.z*dx*dx + a1.x*dy*dy) - a0.w*dx*dy;
        float alpha = fminf(0.99f, a1.y * __expf(power));
        bool ok = (power <= 0.0f) & (alpha >= (1.0f/255.0f)) & (T >= 1e-4f);
        float al = ok ? alpha : 0.0f;
        float wgt = al * T;
        ar += wgt * a1.z;
        ag += wgt * a1.w;
        ab += wgt * cbv;
        T *= (1.0f - al);
        if (((jj & 31) == 31) &&
            __ballot_sync(0xffffffffu, T >= 1e-4f) == 0u) break;
    }

    const int pix = yi * WIMG + xi;
    out_rgb[pix] = ar;
    out_rgb[HIMG * WIMG + pix] = ag;
    out_rgb[2 * HIMG * WIMG + pix] = ab;
}

extern "C" void kernel_launch(void* const* d_in, const int* in_sizes, int n_in,
                              void* d_out, int out_size)
{
    const float* pts    = (const float*)d_in[0];
    const float* scales = (const float*)d_in[1];
    const float* rots   = (const float*)d_in[2];
    const float* opac   = (const float*)d_in[3];
    const float* shs    = (const float*)d_in[4];
    const float* vm     = (const float*)d_in[5];

    float* out = (float*)d_out;
    float* vsp = nullptr;
    float* rad = nullptr;
    const int rgb_n = 3 * HIMG * WIMG;
    if (out_size >= rgb_n + 3 * PN + PN) {
        vsp = out + rgb_n;
        rad = vsp + 3 * PN;
    }

    preprocess_kernel<<<4, 128>>>(pts, scales, rots, opac, shs, vm, vsp, rad);
    sort_kernel<<<4, 128>>>();
    render_kernel<<<256, 256>>>(out);
}